// round 1
// baseline (speedup 1.0000x reference)
#include <cuda_runtime.h>
#include <cuda_bf16.h>
#include <cstdint>
#include <cstddef>

// Problem constants (fixed shapes from reference)
#define BATCH 4
#define SEQ   2048
#define CDIM  1024
#define NHEAD 16
#define HDIM  64
#define MROWS (BATCH * SEQ)          // 8192

// ---------------------------------------------------------------------------
// Scratch (static device globals; no allocation allowed)
// ---------------------------------------------------------------------------
__device__ float g_q[(size_t)MROWS * CDIM];
__device__ float g_k[(size_t)MROWS * CDIM];
__device__ float g_v[(size_t)MROWS * CDIM];
__device__ float g_y[(size_t)MROWS * CDIM];

// ---------------------------------------------------------------------------
// GEMM (NT): C[m,n] = sum_k A[m,k] * B[n,k]
// A: [M,K] row-major, B: [N,K] row-major, C: [M,N] row-major
// Tiles: 128x128x16, 256 threads, 8x8 micro-tile per thread.
// M,N,K all multiples of tile sizes here (8192/1024/1024) -> no bounds checks.
// ---------------------------------------------------------------------------
#define BM 128
#define BN 128
#define BKK 16
#define TM 8
#define TN 8

__global__ __launch_bounds__(256, 2)
void gemm_nt_kernel(const float* __restrict__ A, const float* __restrict__ B,
                    float* __restrict__ C, int M, int N, int K)
{
    __shared__ float As[BKK][BM];
    __shared__ float Bs[BKK][BN];

    const int tid = threadIdx.x;         // 0..255
    const int tx  = tid & 15;            // 16 col-threads
    const int ty  = tid >> 4;            // 16 row-threads
    const int m0  = blockIdx.y * BM;
    const int n0  = blockIdx.x * BN;

    float acc[TM][TN];
#pragma unroll
    for (int i = 0; i < TM; i++)
#pragma unroll
        for (int j = 0; j < TN; j++) acc[i][j] = 0.0f;

    for (int kt = 0; kt < K; kt += BKK) {
        // Load A/B tiles: 128x16 floats each = 512 float4; 2 per thread per matrix.
#pragma unroll
        for (int it = 0; it < 2; it++) {
            int l4 = tid + it * 256;     // 0..511
            int r  = l4 >> 2;            // 0..127
            int cg = (l4 & 3) * 4;       // 0,4,8,12
            float4 va = *reinterpret_cast<const float4*>(&A[(size_t)(m0 + r) * K + kt + cg]);
            As[cg + 0][r] = va.x; As[cg + 1][r] = va.y;
            As[cg + 2][r] = va.z; As[cg + 3][r] = va.w;
            float4 vb = *reinterpret_cast<const float4*>(&B[(size_t)(n0 + r) * K + kt + cg]);
            Bs[cg + 0][r] = vb.x; Bs[cg + 1][r] = vb.y;
            Bs[cg + 2][r] = vb.z; Bs[cg + 3][r] = vb.w;
        }
        __syncthreads();

#pragma unroll
        for (int k = 0; k < BKK; k++) {
            float ar[TM], br[TN];
#pragma unroll
            for (int i = 0; i < TM; i++) ar[i] = As[k][ty * TM + i];
#pragma unroll
            for (int j = 0; j < TN; j++) br[j] = Bs[k][tx * TN + j];
#pragma unroll
            for (int i = 0; i < TM; i++)
#pragma unroll
                for (int j = 0; j < TN; j++)
                    acc[i][j] = fmaf(ar[i], br[j], acc[i][j]);
        }
        __syncthreads();
    }

#pragma unroll
    for (int i = 0; i < TM; i++) {
#pragma unroll
        for (int j4 = 0; j4 < TN; j4 += 4) {
            float4 v = make_float4(acc[i][j4], acc[i][j4 + 1], acc[i][j4 + 2], acc[i][j4 + 3]);
            *reinterpret_cast<float4*>(
                &C[(size_t)(m0 + ty * TM + i) * N + n0 + tx * TN + j4]) = v;
        }
    }
}

// ---------------------------------------------------------------------------
// RoPE + RMSNorm (in-place on q and k).
// One warp handles one (b,t,h) row of 64 dims: lane owns dims {lane, lane+32}.
// rotate_half: rot[d] = -x[d+32] (d<32), rot[d] = x[d-32] (d>=32)
// ---------------------------------------------------------------------------
__global__ __launch_bounds__(128)
void rope_rms_kernel(float* __restrict__ q, float* __restrict__ k,
                     const float* __restrict__ cs, const float* __restrict__ sn)
{
    const int gwarp = (blockIdx.x * blockDim.x + threadIdx.x) >> 5;
    const int lane  = threadIdx.x & 31;
    // gwarp in [0, BATCH*SEQ*NHEAD)
    const int h  = gwarp & (NHEAD - 1);
    const int bt = gwarp >> 4;                 // b*SEQ + t
    const int t  = bt & (SEQ - 1);
    const size_t base = (size_t)bt * CDIM + h * HDIM;

    const float c1 = cs[t * HDIM + lane];
    const float c2 = cs[t * HDIM + 32 + lane];
    const float s1 = sn[t * HDIM + lane];
    const float s2 = sn[t * HDIM + 32 + lane];

    // q
    {
        float x1 = q[base + lane];
        float x2 = q[base + 32 + lane];
        float r1 = x1 * c1 - x2 * s1;
        float r2 = x2 * c2 + x1 * s2;
        float ss = r1 * r1 + r2 * r2;
#pragma unroll
        for (int off = 16; off > 0; off >>= 1)
            ss += __shfl_xor_sync(0xffffffffu, ss, off);
        float inv = rsqrtf(ss * (1.0f / 64.0f) + 1e-6f);
        q[base + lane]      = r1 * inv;
        q[base + 32 + lane] = r2 * inv;
    }
    // k
    {
        float x1 = k[base + lane];
        float x2 = k[base + 32 + lane];
        float r1 = x1 * c1 - x2 * s1;
        float r2 = x2 * c2 + x1 * s2;
        float ss = r1 * r1 + r2 * r2;
#pragma unroll
        for (int off = 16; off > 0; off >>= 1)
            ss += __shfl_xor_sync(0xffffffffu, ss, off);
        float inv = rsqrtf(ss * (1.0f / 64.0f) + 1e-6f);
        k[base + lane]      = r1 * inv;
        k[base + 32 + lane] = r2 * inv;
    }
}

// ---------------------------------------------------------------------------
// Flash attention (fp32, non-causal, full softmax).
// Grid: (qtile=32, h=16, b=4). Block: 256 threads (16x16), 64x64 S tile,
// 4x4 micro-tile per thread. Online softmax. Dynamic shared memory.
// Layout of q/k/v/y: (B,T,H,D) => row stride CDIM, head offset h*HDIM.
// ---------------------------------------------------------------------------
#define ATN_SMEM (4 * 64 * 65 * (int)sizeof(float))

__global__ __launch_bounds__(256)
void attn_kernel(const float* __restrict__ Q, const float* __restrict__ K,
                 const float* __restrict__ V, float* __restrict__ Y)
{
    extern __shared__ float sm[];
    float* Qs = sm;                 // [64][65]
    float* Ks = Qs + 64 * 65;       // [64][65]
    float* Vs = Ks + 64 * 65;       // [64][65]
    float* Ps = Vs + 64 * 65;       // [64][65]

    const int b  = blockIdx.z;
    const int h  = blockIdx.y;
    const int qt = blockIdx.x;
    const int tid = threadIdx.x;
    const int tx  = tid & 15;
    const int ty  = tid >> 4;
    const float scale = 0.125f;     // 1/sqrt(64)

    const float* qbase = Q + ((size_t)b * SEQ + qt * 64) * CDIM + h * HDIM;
    const float* kbase = K + (size_t)b * SEQ * CDIM + h * HDIM;
    const float* vbase = V + (size_t)b * SEQ * CDIM + h * HDIM;

    // Load Q tile (64x64): 1024 float4 loads, 4 per thread
    for (int i = tid; i < 64 * 16; i += 256) {
        int r  = i >> 4;
        int c4 = (i & 15) * 4;
        float4 v = *reinterpret_cast<const float4*>(&qbase[(size_t)r * CDIM + c4]);
        Qs[r * 65 + c4 + 0] = v.x; Qs[r * 65 + c4 + 1] = v.y;
        Qs[r * 65 + c4 + 2] = v.z; Qs[r * 65 + c4 + 3] = v.w;
    }

    float m_i[4], l_i[4], o[4][4];
#pragma unroll
    for (int i = 0; i < 4; i++) {
        m_i[i] = -1e30f; l_i[i] = 0.0f;
#pragma unroll
        for (int j = 0; j < 4; j++) o[i][j] = 0.0f;
    }
    __syncthreads();

    for (int kt = 0; kt < SEQ; kt += 64) {
        // Load K,V tiles
        for (int i = tid; i < 64 * 16; i += 256) {
            int r  = i >> 4;
            int c4 = (i & 15) * 4;
            float4 vk = *reinterpret_cast<const float4*>(&kbase[(size_t)(kt + r) * CDIM + c4]);
            Ks[r * 65 + c4 + 0] = vk.x; Ks[r * 65 + c4 + 1] = vk.y;
            Ks[r * 65 + c4 + 2] = vk.z; Ks[r * 65 + c4 + 3] = vk.w;
            float4 vv = *reinterpret_cast<const float4*>(&vbase[(size_t)(kt + r) * CDIM + c4]);
            Vs[r * 65 + c4 + 0] = vv.x; Vs[r * 65 + c4 + 1] = vv.y;
            Vs[r * 65 + c4 + 2] = vv.z; Vs[r * 65 + c4 + 3] = vv.w;
        }
        __syncthreads();

        // S = Qs @ Ks^T  (4x4 per thread)
        float s[4][4];
#pragma unroll
        for (int i = 0; i < 4; i++)
#pragma unroll
            for (int j = 0; j < 4; j++) s[i][j] = 0.0f;

#pragma unroll 8
        for (int d = 0; d < 64; d++) {
            float a[4], bb[4];
#pragma unroll
            for (int i = 0; i < 4; i++) a[i]  = Qs[(ty * 4 + i) * 65 + d];
#pragma unroll
            for (int j = 0; j < 4; j++) bb[j] = Ks[(tx * 4 + j) * 65 + d];
#pragma unroll
            for (int i = 0; i < 4; i++)
#pragma unroll
                for (int j = 0; j < 4; j++)
                    s[i][j] = fmaf(a[i], bb[j], s[i][j]);
        }

        // Online softmax per row (rows owned by same 16-lane group share ty)
#pragma unroll
        for (int i = 0; i < 4; i++) {
            float mx = -1e30f;
#pragma unroll
            for (int j = 0; j < 4; j++) {
                s[i][j] *= scale;
                mx = fmaxf(mx, s[i][j]);
            }
#pragma unroll
            for (int off = 8; off > 0; off >>= 1)
                mx = fmaxf(mx, __shfl_xor_sync(0xffffffffu, mx, off));
            float mnew  = fmaxf(m_i[i], mx);
            float alpha = __expf(m_i[i] - mnew);
            float rsum = 0.0f;
#pragma unroll
            for (int j = 0; j < 4; j++) {
                float p = __expf(s[i][j] - mnew);
                Ps[(ty * 4 + i) * 65 + tx * 4 + j] = p;
                rsum += p;
            }
#pragma unroll
            for (int off = 8; off > 0; off >>= 1)
                rsum += __shfl_xor_sync(0xffffffffu, rsum, off);
            l_i[i] = l_i[i] * alpha + rsum;
            m_i[i] = mnew;
#pragma unroll
            for (int j = 0; j < 4; j++) o[i][j] *= alpha;
        }
        __syncthreads();

        // O += Ps @ Vs
#pragma unroll 8
        for (int n = 0; n < 64; n++) {
            float pv[4], vv[4];
#pragma unroll
            for (int i = 0; i < 4; i++) pv[i] = Ps[(ty * 4 + i) * 65 + n];
#pragma unroll
            for (int j = 0; j < 4; j++) vv[j] = Vs[n * 65 + tx * 4 + j];
#pragma unroll
            for (int i = 0; i < 4; i++)
#pragma unroll
                for (int j = 0; j < 4; j++)
                    o[i][j] = fmaf(pv[i], vv[j], o[i][j]);
        }
        __syncthreads();
    }

    // Epilogue: normalize and store to y (B,T,H,D)
    float* ybase = Y + ((size_t)b * SEQ + qt * 64) * CDIM + h * HDIM;
#pragma unroll
    for (int i = 0; i < 4; i++) {
        float inv = 1.0f / l_i[i];
#pragma unroll
        for (int j = 0; j < 4; j++)
            ybase[(size_t)(ty * 4 + i) * CDIM + tx * 4 + j] = o[i][j] * inv;
    }
}

// ---------------------------------------------------------------------------
// kernel_launch
// Inputs (metadata order): x, cos, sin, Wq, Wk, Wv, Wo
// ---------------------------------------------------------------------------
extern "C" void kernel_launch(void* const* d_in, const int* in_sizes, int n_in,
                              void* d_out, int out_size)
{
    const float* x   = (const float*)d_in[0];
    const float* cs  = (const float*)d_in[1];
    const float* sn  = (const float*)d_in[2];
    const float* Wq  = (const float*)d_in[3];
    const float* Wk  = (const float*)d_in[4];
    const float* Wv  = (const float*)d_in[5];
    const float* Wo  = (const float*)d_in[6];
    float* out = (float*)d_out;

    float *q, *k, *v, *y;
    cudaGetSymbolAddress((void**)&q, g_q);
    cudaGetSymbolAddress((void**)&k, g_k);
    cudaGetSymbolAddress((void**)&v, g_v);
    cudaGetSymbolAddress((void**)&y, g_y);

    cudaFuncSetAttribute(attn_kernel, cudaFuncAttributeMaxDynamicSharedMemorySize, ATN_SMEM);

    dim3 ggrid(CDIM / BN, MROWS / BM);   // (8, 64)
    gemm_nt_kernel<<<ggrid, 256>>>(x, Wq, q, MROWS, CDIM, CDIM);
    gemm_nt_kernel<<<ggrid, 256>>>(x, Wk, k, MROWS, CDIM, CDIM);
    gemm_nt_kernel<<<ggrid, 256>>>(x, Wv, v, MROWS, CDIM, CDIM);

    // RoPE + RMSNorm: one warp per (b,t,h) row; 128-thread blocks -> 4 rows/block
    int nwarps = BATCH * SEQ * NHEAD;    // 131072
    rope_rms_kernel<<<nwarps / 4, 128>>>(q, k, cs, sn);

    dim3 agrid(SEQ / 64, NHEAD, BATCH);  // (32, 16, 4)
    attn_kernel<<<agrid, 256, ATN_SMEM>>>(q, k, v, y);

    gemm_nt_kernel<<<ggrid, 256>>>(y, Wo, out, MROWS, CDIM, CDIM);
}

// round 4
// speedup vs baseline: 1.4106x; 1.4106x over previous
#include <cuda_runtime.h>
#include <cuda_bf16.h>
#include <cstdint>
#include <cstddef>

// Problem constants (fixed shapes from reference)
#define BATCH 4
#define SEQ   2048
#define CDIM  1024
#define NHEAD 16
#define HDIM  64
#define MROWS (BATCH * SEQ)          // 8192

// ---------------------------------------------------------------------------
// Scratch (static device globals; no allocation allowed)
// ---------------------------------------------------------------------------
__device__ float g_q[(size_t)MROWS * CDIM];
__device__ float g_k[(size_t)MROWS * CDIM];
__device__ float g_v[(size_t)MROWS * CDIM];
__device__ float g_y[(size_t)MROWS * CDIM];

__device__ __nv_bfloat16 g_xhi[(size_t)MROWS * CDIM];
__device__ __nv_bfloat16 g_xlo[(size_t)MROWS * CDIM];
__device__ __nv_bfloat16 g_yhi[(size_t)MROWS * CDIM];
__device__ __nv_bfloat16 g_ylo[(size_t)MROWS * CDIM];
__device__ __nv_bfloat16 g_whi[4 * (size_t)CDIM * CDIM];
__device__ __nv_bfloat16 g_wlo[4 * (size_t)CDIM * CDIM];

// ---------------------------------------------------------------------------
// fp32 -> (bf16 hi, bf16 lo) split conversion. n divisible by 4.
// ---------------------------------------------------------------------------
__global__ __launch_bounds__(256)
void cvt_bf16x2_kernel(const float4* __restrict__ x,
                       __nv_bfloat162* __restrict__ hi,
                       __nv_bfloat162* __restrict__ lo, int n4)
{
    int i = blockIdx.x * blockDim.x + threadIdx.x;
    if (i >= n4) return;
    float4 v = x[i];
    __nv_bfloat16 h0 = __float2bfloat16(v.x);
    __nv_bfloat16 h1 = __float2bfloat16(v.y);
    __nv_bfloat16 h2 = __float2bfloat16(v.z);
    __nv_bfloat16 h3 = __float2bfloat16(v.w);
    __nv_bfloat16 l0 = __float2bfloat16(v.x - __bfloat162float(h0));
    __nv_bfloat16 l1 = __float2bfloat16(v.y - __bfloat162float(h1));
    __nv_bfloat16 l2 = __float2bfloat16(v.z - __bfloat162float(h2));
    __nv_bfloat16 l3 = __float2bfloat16(v.w - __bfloat162float(h3));
    hi[i * 2 + 0] = __nv_bfloat162(h0, h1);
    hi[i * 2 + 1] = __nv_bfloat162(h2, h3);
    lo[i * 2 + 0] = __nv_bfloat162(l0, l1);
    lo[i * 2 + 1] = __nv_bfloat162(l2, l3);
}

// ---------------------------------------------------------------------------
// MMA helpers (legacy warp-level tensor core path; valid on compute_103 PTX)
// ---------------------------------------------------------------------------
__device__ __forceinline__ uint32_t smem_u32(const void* p) {
    return (uint32_t)__cvta_generic_to_shared(p);
}

__device__ __forceinline__ void ldsm_x4(uint32_t addr, uint32_t& r0, uint32_t& r1,
                                        uint32_t& r2, uint32_t& r3) {
    asm volatile("ldmatrix.sync.aligned.m8n8.x4.shared.b16 {%0,%1,%2,%3}, [%4];"
                 : "=r"(r0), "=r"(r1), "=r"(r2), "=r"(r3) : "r"(addr));
}

__device__ __forceinline__ void mma_bf16(float* c, uint32_t a0, uint32_t a1,
                                         uint32_t a2, uint32_t a3,
                                         uint32_t b0, uint32_t b1) {
    asm volatile(
        "mma.sync.aligned.m16n8k16.row.col.f32.bf16.bf16.f32 "
        "{%0,%1,%2,%3}, {%4,%5,%6,%7}, {%8,%9}, {%0,%1,%2,%3};"
        : "+f"(c[0]), "+f"(c[1]), "+f"(c[2]), "+f"(c[3])
        : "r"(a0), "r"(a1), "r"(a2), "r"(a3), "r"(b0), "r"(b1));
}

__device__ __forceinline__ void cp_async16(uint32_t smem_dst, const void* gmem_src) {
    asm volatile("cp.async.cg.shared.global [%0], [%1], 16;"
                 :: "r"(smem_dst), "l"(gmem_src) : "memory");
}
__device__ __forceinline__ void cp_async_commit_wait0() {
    asm volatile("cp.async.commit_group;" ::: "memory");
    asm volatile("cp.async.wait_group 0;" ::: "memory");
}

// ---------------------------------------------------------------------------
// bf16x3 GEMM (NT): C[m,n] = sum_k A[m,k]*B[n,k], fp32 out.
// C = Ah*Bh + Ah*Bl + Al*Bh with fp32 mma accumulators.
// Tile: 128x128, BK=64 bf16. 8 warps in 4(m) x 2(n); warp tile 32x64.
// Smem rows padded to 72 bf16 (144B) -> conflict-free ldmatrix.
// ---------------------------------------------------------------------------
#define GBK       64
#define LDS_STR   72                      // bf16 elements per smem row
#define LDS_STRB  (LDS_STR * 2)           // 144 bytes
#define TILE_B    (128 * LDS_STRB)        // 18432 bytes per operand tile
#define OFF_AHI   0
#define OFF_ALO   (1 * TILE_B)
#define OFF_BHI   (2 * TILE_B)
#define OFF_BLO   (3 * TILE_B)
#define GEMM_SMEM (4 * TILE_B)            // 73728 bytes

__global__ __launch_bounds__(256, 2)
void gemm_mma_kernel(const __nv_bfloat16* __restrict__ Ahi,
                     const __nv_bfloat16* __restrict__ Alo,
                     const __nv_bfloat16* __restrict__ Bhi,
                     const __nv_bfloat16* __restrict__ Blo,
                     float* __restrict__ C, int M, int N, int K)
{
    extern __shared__ char sm[];
    const int tid  = threadIdx.x;
    const int warp = tid >> 5;
    const int lane = tid & 31;
    const int wm   = warp & 3;            // 0..3  (m direction, 32 rows each)
    const int wn   = warp >> 2;           // 0..1  (n direction, 64 cols each)
    const int m0   = blockIdx.y * 128;
    const int n0   = blockIdx.x * 128;

    const uint32_t sbase = smem_u32(sm);

    float acc[2][8][4];
#pragma unroll
    for (int i = 0; i < 2; i++)
#pragma unroll
        for (int j = 0; j < 8; j++)
#pragma unroll
            for (int t = 0; t < 4; t++) acc[i][j][t] = 0.0f;

    const char* pAh = (const char*)(Ahi + (size_t)m0 * K);
    const char* pAl = (const char*)(Alo + (size_t)m0 * K);
    const char* pBh = (const char*)(Bhi + (size_t)n0 * K);
    const char* pBl = (const char*)(Blo + (size_t)n0 * K);
    const size_t rowb = (size_t)K * 2;

    // ldmatrix source addresses (per lane), constant across chunks
    // A: row = wm*32 + mt*16 + (lane&15); col bytes = kk*32 + (lane>>4)*16
    const int lrow = lane & 15;
    const int lcol = (lane >> 4) * 16;

    const int nch = K / GBK;
    for (int ch = 0; ch < nch; ch++) {
        const size_t koff = (size_t)ch * (GBK * 2);   // bytes
        // G->S: 4 tiles x 128 rows x 128 data bytes; 8 uint4 per row.
#pragma unroll
        for (int it = 0; it < 4; it++) {
            int i  = tid + it * 256;       // 0..1023
            int r  = i >> 3;
            int cb = (i & 7) * 16;
            size_t   go = (size_t)r * rowb + koff + cb;
            uint32_t so = r * LDS_STRB + cb;
            cp_async16(sbase + OFF_AHI + so, pAh + go);
            cp_async16(sbase + OFF_ALO + so, pAl + go);
            cp_async16(sbase + OFF_BHI + so, pBh + go);
            cp_async16(sbase + OFF_BLO + so, pBl + go);
        }
        cp_async_commit_wait0();
        __syncthreads();

#pragma unroll
        for (int kk = 0; kk < GBK / 16; kk++) {
            const uint32_t kbyte = kk * 32 + lcol;
            // B fragments for this k16: 8 ntiles (pairs loaded via x4), hi & lo
            uint32_t bh[8][2], bl[8][2];
#pragma unroll
            for (int np = 0; np < 4; np++) {   // each x4 covers 2 ntiles
                uint32_t baddr = sbase + OFF_BHI +
                                 (wn * 64 + np * 16 + lrow) * LDS_STRB + kbyte;
                ldsm_x4(baddr, bh[np * 2][0], bh[np * 2 + 1][0],
                               bh[np * 2][1], bh[np * 2 + 1][1]);
                uint32_t laddr = baddr + (OFF_BLO - OFF_BHI);
                ldsm_x4(laddr, bl[np * 2][0], bl[np * 2 + 1][0],
                               bl[np * 2][1], bl[np * 2 + 1][1]);
            }
#pragma unroll
            for (int mt = 0; mt < 2; mt++) {
                uint32_t aaddr = sbase + OFF_AHI +
                                 (wm * 32 + mt * 16 + lrow) * LDS_STRB + kbyte;
                uint32_t ah0, ah1, ah2, ah3, al0, al1, al2, al3;
                ldsm_x4(aaddr, ah0, ah1, ah2, ah3);
                ldsm_x4(aaddr + (OFF_ALO - OFF_AHI), al0, al1, al2, al3);
#pragma unroll
                for (int nt = 0; nt < 8; nt++) {
                    mma_bf16(acc[mt][nt], ah0, ah1, ah2, ah3, bh[nt][0], bh[nt][1]);
                    mma_bf16(acc[mt][nt], ah0, ah1, ah2, ah3, bl[nt][0], bl[nt][1]);
                    mma_bf16(acc[mt][nt], al0, al1, al2, al3, bh[nt][0], bh[nt][1]);
                }
            }
        }
        __syncthreads();
    }

    // Epilogue: c0,c1 -> (row, col..col+1); c2,c3 -> (row+8, col..col+1)
    const int qrow = lane >> 2;
    const int qcol = (lane & 3) * 2;
#pragma unroll
    for (int mt = 0; mt < 2; mt++) {
        const int r0 = m0 + wm * 32 + mt * 16 + qrow;
#pragma unroll
        for (int nt = 0; nt < 8; nt++) {
            const int c = n0 + wn * 64 + nt * 8 + qcol;
            *reinterpret_cast<float2*>(&C[(size_t)r0 * N + c]) =
                make_float2(acc[mt][nt][0], acc[mt][nt][1]);
            *reinterpret_cast<float2*>(&C[(size_t)(r0 + 8) * N + c]) =
                make_float2(acc[mt][nt][2], acc[mt][nt][3]);
        }
    }
}

// ---------------------------------------------------------------------------
// RoPE + RMSNorm (in-place on q and k). One warp per (b,t,h) row.
// ---------------------------------------------------------------------------
__global__ __launch_bounds__(128)
void rope_rms_kernel(float* __restrict__ q, float* __restrict__ k,
                     const float* __restrict__ cs, const float* __restrict__ sn)
{
    const int gwarp = (blockIdx.x * blockDim.x + threadIdx.x) >> 5;
    const int lane  = threadIdx.x & 31;
    const int h  = gwarp & (NHEAD - 1);
    const int bt = gwarp >> 4;
    const int t  = bt & (SEQ - 1);
    const size_t base = (size_t)bt * CDIM + h * HDIM;

    const float c1 = cs[t * HDIM + lane];
    const float c2 = cs[t * HDIM + 32 + lane];
    const float s1 = sn[t * HDIM + lane];
    const float s2 = sn[t * HDIM + 32 + lane];

    {
        float x1 = q[base + lane];
        float x2 = q[base + 32 + lane];
        float r1 = x1 * c1 - x2 * s1;
        float r2 = x2 * c2 + x1 * s2;
        float ss = r1 * r1 + r2 * r2;
#pragma unroll
        for (int off = 16; off > 0; off >>= 1)
            ss += __shfl_xor_sync(0xffffffffu, ss, off);
        float inv = rsqrtf(ss * (1.0f / 64.0f) + 1e-6f);
        q[base + lane]      = r1 * inv;
        q[base + 32 + lane] = r2 * inv;
    }
    {
        float x1 = k[base + lane];
        float x2 = k[base + 32 + lane];
        float r1 = x1 * c1 - x2 * s1;
        float r2 = x2 * c2 + x1 * s2;
        float ss = r1 * r1 + r2 * r2;
#pragma unroll
        for (int off = 16; off > 0; off >>= 1)
            ss += __shfl_xor_sync(0xffffffffu, ss, off);
        float inv = rsqrtf(ss * (1.0f / 64.0f) + 1e-6f);
        k[base + lane]      = r1 * inv;
        k[base + 32 + lane] = r2 * inv;
    }
}

// ---------------------------------------------------------------------------
// Flash attention (fp32, non-causal, online softmax). 64x64 tiles.
// ---------------------------------------------------------------------------
#define ATN_SMEM (4 * 64 * 65 * (int)sizeof(float))

__global__ __launch_bounds__(256)
void attn_kernel(const float* __restrict__ Q, const float* __restrict__ K,
                 const float* __restrict__ V, float* __restrict__ Y)
{
    extern __shared__ float smf[];
    float* Qs = smf;
    float* Ks = Qs + 64 * 65;
    float* Vs = Ks + 64 * 65;
    float* Ps = Vs + 64 * 65;

    const int b  = blockIdx.z;
    const int h  = blockIdx.y;
    const int qt = blockIdx.x;
    const int tid = threadIdx.x;
    const int tx  = tid & 15;
    const int ty  = tid >> 4;
    const float scale = 0.125f;

    const float* qbase = Q + ((size_t)b * SEQ + qt * 64) * CDIM + h * HDIM;
    const float* kbase = K + (size_t)b * SEQ * CDIM + h * HDIM;
    const float* vbase = V + (size_t)b * SEQ * CDIM + h * HDIM;

    for (int i = tid; i < 64 * 16; i += 256) {
        int r  = i >> 4;
        int c4 = (i & 15) * 4;
        float4 v = *reinterpret_cast<const float4*>(&qbase[(size_t)r * CDIM + c4]);
        Qs[r * 65 + c4 + 0] = v.x; Qs[r * 65 + c4 + 1] = v.y;
        Qs[r * 65 + c4 + 2] = v.z; Qs[r * 65 + c4 + 3] = v.w;
    }

    float m_i[4], l_i[4], o[4][4];
#pragma unroll
    for (int i = 0; i < 4; i++) {
        m_i[i] = -1e30f; l_i[i] = 0.0f;
#pragma unroll
        for (int j = 0; j < 4; j++) o[i][j] = 0.0f;
    }
    __syncthreads();

    for (int kt = 0; kt < SEQ; kt += 64) {
        for (int i = tid; i < 64 * 16; i += 256) {
            int r  = i >> 4;
            int c4 = (i & 15) * 4;
            float4 vk = *reinterpret_cast<const float4*>(&kbase[(size_t)(kt + r) * CDIM + c4]);
            Ks[r * 65 + c4 + 0] = vk.x; Ks[r * 65 + c4 + 1] = vk.y;
            Ks[r * 65 + c4 + 2] = vk.z; Ks[r * 65 + c4 + 3] = vk.w;
            float4 vv = *reinterpret_cast<const float4*>(&vbase[(size_t)(kt + r) * CDIM + c4]);
            Vs[r * 65 + c4 + 0] = vv.x; Vs[r * 65 + c4 + 1] = vv.y;
            Vs[r * 65 + c4 + 2] = vv.z; Vs[r * 65 + c4 + 3] = vv.w;
        }
        __syncthreads();

        float s[4][4];
#pragma unroll
        for (int i = 0; i < 4; i++)
#pragma unroll
            for (int j = 0; j < 4; j++) s[i][j] = 0.0f;

#pragma unroll 8
        for (int d = 0; d < 64; d++) {
            float a[4], bb[4];
#pragma unroll
            for (int i = 0; i < 4; i++) a[i]  = Qs[(ty * 4 + i) * 65 + d];
#pragma unroll
            for (int j = 0; j < 4; j++) bb[j] = Ks[(tx * 4 + j) * 65 + d];
#pragma unroll
            for (int i = 0; i < 4; i++)
#pragma unroll
                for (int j = 0; j < 4; j++)
                    s[i][j] = fmaf(a[i], bb[j], s[i][j]);
        }

#pragma unroll
        for (int i = 0; i < 4; i++) {
            float mx = -1e30f;
#pragma unroll
            for (int j = 0; j < 4; j++) {
                s[i][j] *= scale;
                mx = fmaxf(mx, s[i][j]);
            }
#pragma unroll
            for (int off = 8; off > 0; off >>= 1)
                mx = fmaxf(mx, __shfl_xor_sync(0xffffffffu, mx, off));
            float mnew  = fmaxf(m_i[i], mx);
            float alpha = __expf(m_i[i] - mnew);
            float rsum = 0.0f;
#pragma unroll
            for (int j = 0; j < 4; j++) {
                float p = __expf(s[i][j] - mnew);
                Ps[(ty * 4 + i) * 65 + tx * 4 + j] = p;
                rsum += p;
            }
#pragma unroll
            for (int off = 8; off > 0; off >>= 1)
                rsum += __shfl_xor_sync(0xffffffffu, rsum, off);
            l_i[i] = l_i[i] * alpha + rsum;
            m_i[i] = mnew;
#pragma unroll
            for (int j = 0; j < 4; j++) o[i][j] *= alpha;
        }
        __syncthreads();

#pragma unroll 8
        for (int n = 0; n < 64; n++) {
            float pv[4], vv[4];
#pragma unroll
            for (int i = 0; i < 4; i++) pv[i] = Ps[(ty * 4 + i) * 65 + n];
#pragma unroll
            for (int j = 0; j < 4; j++) vv[j] = Vs[n * 65 + tx * 4 + j];
#pragma unroll
            for (int i = 0; i < 4; i++)
#pragma unroll
                for (int j = 0; j < 4; j++)
                    o[i][j] = fmaf(pv[i], vv[j], o[i][j]);
        }
        __syncthreads();
    }

    float* ybase = Y + ((size_t)b * SEQ + qt * 64) * CDIM + h * HDIM;
#pragma unroll
    for (int i = 0; i < 4; i++) {
        float inv = 1.0f / l_i[i];
#pragma unroll
        for (int j = 0; j < 4; j++)
            ybase[(size_t)(ty * 4 + i) * CDIM + tx * 4 + j] = o[i][j] * inv;
    }
}

// ---------------------------------------------------------------------------
// kernel_launch
// Inputs (metadata order): x, cos, sin, Wq, Wk, Wv, Wo
// ---------------------------------------------------------------------------
extern "C" void kernel_launch(void* const* d_in, const int* in_sizes, int n_in,
                              void* d_out, int out_size)
{
    const float* x   = (const float*)d_in[0];
    const float* cs  = (const float*)d_in[1];
    const float* sn  = (const float*)d_in[2];
    const float* Wq  = (const float*)d_in[3];
    const float* Wk  = (const float*)d_in[4];
    const float* Wv  = (const float*)d_in[5];
    const float* Wo  = (const float*)d_in[6];
    float* out = (float*)d_out;

    float *q, *k, *v, *y;
    cudaGetSymbolAddress((void**)&q, g_q);
    cudaGetSymbolAddress((void**)&k, g_k);
    cudaGetSymbolAddress((void**)&v, g_v);
    cudaGetSymbolAddress((void**)&y, g_y);
    __nv_bfloat16 *xhi, *xlo, *yhi, *ylo, *whi, *wlo;
    cudaGetSymbolAddress((void**)&xhi, g_xhi);
    cudaGetSymbolAddress((void**)&xlo, g_xlo);
    cudaGetSymbolAddress((void**)&yhi, g_yhi);
    cudaGetSymbolAddress((void**)&ylo, g_ylo);
    cudaGetSymbolAddress((void**)&whi, g_whi);
    cudaGetSymbolAddress((void**)&wlo, g_wlo);

    cudaFuncSetAttribute(attn_kernel, cudaFuncAttributeMaxDynamicSharedMemorySize, ATN_SMEM);
    cudaFuncSetAttribute(gemm_mma_kernel, cudaFuncAttributeMaxDynamicSharedMemorySize, GEMM_SMEM);

    const size_t wsz = (size_t)CDIM * CDIM;    // 1M elements per weight

    // Split x and weights into bf16 hi/lo pairs
    {
        int n4 = (int)((size_t)MROWS * CDIM / 4);
        cvt_bf16x2_kernel<<<(n4 + 255) / 256, 256>>>(
            (const float4*)x, (__nv_bfloat162*)xhi, (__nv_bfloat162*)xlo, n4);
        int w4 = (int)(wsz / 4);
        cvt_bf16x2_kernel<<<(w4 + 255) / 256, 256>>>(
            (const float4*)Wq, (__nv_bfloat162*)(whi + 0 * wsz), (__nv_bfloat162*)(wlo + 0 * wsz), w4);
        cvt_bf16x2_kernel<<<(w4 + 255) / 256, 256>>>(
            (const float4*)Wk, (__nv_bfloat162*)(whi + 1 * wsz), (__nv_bfloat162*)(wlo + 1 * wsz), w4);
        cvt_bf16x2_kernel<<<(w4 + 255) / 256, 256>>>(
            (const float4*)Wv, (__nv_bfloat162*)(whi + 2 * wsz), (__nv_bfloat162*)(wlo + 2 * wsz), w4);
        cvt_bf16x2_kernel<<<(w4 + 255) / 256, 256>>>(
            (const float4*)Wo, (__nv_bfloat162*)(whi + 3 * wsz), (__nv_bfloat162*)(wlo + 3 * wsz), w4);
    }

    dim3 ggrid(CDIM / 128, MROWS / 128);   // (8, 64)
    gemm_mma_kernel<<<ggrid, 256, GEMM_SMEM>>>(xhi, xlo, whi + 0 * wsz, wlo + 0 * wsz, q, MROWS, CDIM, CDIM);
    gemm_mma_kernel<<<ggrid, 256, GEMM_SMEM>>>(xhi, xlo, whi + 1 * wsz, wlo + 1 * wsz, k, MROWS, CDIM, CDIM);
    gemm_mma_kernel<<<ggrid, 256, GEMM_SMEM>>>(xhi, xlo, whi + 2 * wsz, wlo + 2 * wsz, v, MROWS, CDIM, CDIM);

    int nwarps = BATCH * SEQ * NHEAD;
    rope_rms_kernel<<<nwarps / 4, 128>>>(q, k, cs, sn);

    dim3 agrid(SEQ / 64, NHEAD, BATCH);
    attn_kernel<<<agrid, 256, ATN_SMEM>>>(q, k, v, y);

    {
        int n4 = (int)((size_t)MROWS * CDIM / 4);
        cvt_bf16x2_kernel<<<(n4 + 255) / 256, 256>>>(
            (const float4*)y, (__nv_bfloat162*)yhi, (__nv_bfloat162*)ylo, n4);
    }
    gemm_mma_kernel<<<ggrid, 256, GEMM_SMEM>>>(yhi, ylo, whi + 3 * wsz, wlo + 3 * wsz, out, MROWS, CDIM, CDIM);
}

// round 5
// speedup vs baseline: 2.6529x; 1.8807x over previous
#include <cuda_runtime.h>
#include <cuda_bf16.h>
#include <cstdint>
#include <cstddef>

// Problem constants (fixed shapes from reference)
#define BATCH 4
#define SEQ   2048
#define CDIM  1024
#define NHEAD 16
#define HDIM  64
#define MROWS (BATCH * SEQ)          // 8192

// ---------------------------------------------------------------------------
// Scratch (static device globals; no allocation allowed)
// ---------------------------------------------------------------------------
__device__ float g_q[(size_t)MROWS * CDIM];
__device__ float g_k[(size_t)MROWS * CDIM];
__device__ float g_v[(size_t)MROWS * CDIM];
__device__ float g_y[(size_t)MROWS * CDIM];

__device__ __nv_bfloat16 g_xhi[(size_t)MROWS * CDIM];
__device__ __nv_bfloat16 g_xlo[(size_t)MROWS * CDIM];
__device__ __nv_bfloat16 g_yhi[(size_t)MROWS * CDIM];
__device__ __nv_bfloat16 g_ylo[(size_t)MROWS * CDIM];
__device__ __nv_bfloat16 g_whi[4 * (size_t)CDIM * CDIM];
__device__ __nv_bfloat16 g_wlo[4 * (size_t)CDIM * CDIM];

// ---------------------------------------------------------------------------
// fp32 -> (bf16 hi, bf16 lo) split conversion. n divisible by 4.
// ---------------------------------------------------------------------------
__global__ __launch_bounds__(256)
void cvt_bf16x2_kernel(const float4* __restrict__ x,
                       __nv_bfloat162* __restrict__ hi,
                       __nv_bfloat162* __restrict__ lo, int n4)
{
    int i = blockIdx.x * blockDim.x + threadIdx.x;
    if (i >= n4) return;
    float4 v = x[i];
    __nv_bfloat16 h0 = __float2bfloat16(v.x);
    __nv_bfloat16 h1 = __float2bfloat16(v.y);
    __nv_bfloat16 h2 = __float2bfloat16(v.z);
    __nv_bfloat16 h3 = __float2bfloat16(v.w);
    __nv_bfloat16 l0 = __float2bfloat16(v.x - __bfloat162float(h0));
    __nv_bfloat16 l1 = __float2bfloat16(v.y - __bfloat162float(h1));
    __nv_bfloat16 l2 = __float2bfloat16(v.z - __bfloat162float(h2));
    __nv_bfloat16 l3 = __float2bfloat16(v.w - __bfloat162float(h3));
    hi[i * 2 + 0] = __nv_bfloat162(h0, h1);
    hi[i * 2 + 1] = __nv_bfloat162(h2, h3);
    lo[i * 2 + 0] = __nv_bfloat162(l0, l1);
    lo[i * 2 + 1] = __nv_bfloat162(l2, l3);
}

// ---------------------------------------------------------------------------
// MMA helpers (legacy warp-level tensor core path; valid on compute_103 PTX)
// ---------------------------------------------------------------------------
__device__ __forceinline__ uint32_t smem_u32(const void* p) {
    return (uint32_t)__cvta_generic_to_shared(p);
}

__device__ __forceinline__ void ldsm_x4(uint32_t addr, uint32_t& r0, uint32_t& r1,
                                        uint32_t& r2, uint32_t& r3) {
    asm volatile("ldmatrix.sync.aligned.m8n8.x4.shared.b16 {%0,%1,%2,%3}, [%4];"
                 : "=r"(r0), "=r"(r1), "=r"(r2), "=r"(r3) : "r"(addr));
}

__device__ __forceinline__ void mma_bf16(float* c, uint32_t a0, uint32_t a1,
                                         uint32_t a2, uint32_t a3,
                                         uint32_t b0, uint32_t b1) {
    asm volatile(
        "mma.sync.aligned.m16n8k16.row.col.f32.bf16.bf16.f32 "
        "{%0,%1,%2,%3}, {%4,%5,%6,%7}, {%8,%9}, {%0,%1,%2,%3};"
        : "+f"(c[0]), "+f"(c[1]), "+f"(c[2]), "+f"(c[3])
        : "r"(a0), "r"(a1), "r"(a2), "r"(a3), "r"(b0), "r"(b1));
}

__device__ __forceinline__ void mma_tf32(float* c, uint32_t a0, uint32_t a1,
                                         uint32_t a2, uint32_t a3,
                                         uint32_t b0, uint32_t b1) {
    asm volatile(
        "mma.sync.aligned.m16n8k8.row.col.f32.tf32.tf32.f32 "
        "{%0,%1,%2,%3}, {%4,%5,%6,%7}, {%8,%9}, {%0,%1,%2,%3};"
        : "+f"(c[0]), "+f"(c[1]), "+f"(c[2]), "+f"(c[3])
        : "r"(a0), "r"(a1), "r"(a2), "r"(a3), "r"(b0), "r"(b1));
}

__device__ __forceinline__ uint32_t f2tf32(float x) {
    uint32_t r;
    asm volatile("cvt.rna.tf32.f32 %0, %1;" : "=r"(r) : "f"(x));
    return r;
}

__device__ __forceinline__ void cp_async16(uint32_t smem_dst, const void* gmem_src) {
    asm volatile("cp.async.cg.shared.global [%0], [%1], 16;"
                 :: "r"(smem_dst), "l"(gmem_src) : "memory");
}
__device__ __forceinline__ void cp_async_commit_wait0() {
    asm volatile("cp.async.commit_group;" ::: "memory");
    asm volatile("cp.async.wait_group 0;" ::: "memory");
}

// ---------------------------------------------------------------------------
// bf16x3 GEMM (NT): C[m,n] = sum_k A[m,k]*B[n,k], fp32 out.
// C = Ah*Bh + Ah*Bl + Al*Bh with fp32 mma accumulators.
// Tile: 128x128, BK=64 bf16. 8 warps in 4(m) x 2(n); warp tile 32x64.
// Smem rows padded to 72 bf16 (144B) -> conflict-free ldmatrix.
// ---------------------------------------------------------------------------
#define GBK       64
#define LDS_STR   72                      // bf16 elements per smem row
#define LDS_STRB  (LDS_STR * 2)           // 144 bytes
#define TILE_B    (128 * LDS_STRB)        // 18432 bytes per operand tile
#define OFF_AHI   0
#define OFF_ALO   (1 * TILE_B)
#define OFF_BHI   (2 * TILE_B)
#define OFF_BLO   (3 * TILE_B)
#define GEMM_SMEM (4 * TILE_B)            // 73728 bytes

__global__ __launch_bounds__(256, 2)
void gemm_mma_kernel(const __nv_bfloat16* __restrict__ Ahi,
                     const __nv_bfloat16* __restrict__ Alo,
                     const __nv_bfloat16* __restrict__ Bhi,
                     const __nv_bfloat16* __restrict__ Blo,
                     float* __restrict__ C, int M, int N, int K)
{
    extern __shared__ char sm[];
    const int tid  = threadIdx.x;
    const int warp = tid >> 5;
    const int lane = tid & 31;
    const int wm   = warp & 3;            // 0..3  (m direction, 32 rows each)
    const int wn   = warp >> 2;           // 0..1  (n direction, 64 cols each)
    const int m0   = blockIdx.y * 128;
    const int n0   = blockIdx.x * 128;

    const uint32_t sbase = smem_u32(sm);

    float acc[2][8][4];
#pragma unroll
    for (int i = 0; i < 2; i++)
#pragma unroll
        for (int j = 0; j < 8; j++)
#pragma unroll
            for (int t = 0; t < 4; t++) acc[i][j][t] = 0.0f;

    const char* pAh = (const char*)(Ahi + (size_t)m0 * K);
    const char* pAl = (const char*)(Alo + (size_t)m0 * K);
    const char* pBh = (const char*)(Bhi + (size_t)n0 * K);
    const char* pBl = (const char*)(Blo + (size_t)n0 * K);
    const size_t rowb = (size_t)K * 2;

    const int lrow = lane & 15;
    const int lcol = (lane >> 4) * 16;

    const int nch = K / GBK;
    for (int ch = 0; ch < nch; ch++) {
        const size_t koff = (size_t)ch * (GBK * 2);   // bytes
#pragma unroll
        for (int it = 0; it < 4; it++) {
            int i  = tid + it * 256;       // 0..1023
            int r  = i >> 3;
            int cb = (i & 7) * 16;
            size_t   go = (size_t)r * rowb + koff + cb;
            uint32_t so = r * LDS_STRB + cb;
            cp_async16(sbase + OFF_AHI + so, pAh + go);
            cp_async16(sbase + OFF_ALO + so, pAl + go);
            cp_async16(sbase + OFF_BHI + so, pBh + go);
            cp_async16(sbase + OFF_BLO + so, pBl + go);
        }
        cp_async_commit_wait0();
        __syncthreads();

#pragma unroll
        for (int kk = 0; kk < GBK / 16; kk++) {
            const uint32_t kbyte = kk * 32 + lcol;
            uint32_t bh[8][2], bl[8][2];
#pragma unroll
            for (int np = 0; np < 4; np++) {
                uint32_t baddr = sbase + OFF_BHI +
                                 (wn * 64 + np * 16 + lrow) * LDS_STRB + kbyte;
                ldsm_x4(baddr, bh[np * 2][0], bh[np * 2 + 1][0],
                               bh[np * 2][1], bh[np * 2 + 1][1]);
                uint32_t laddr = baddr + (OFF_BLO - OFF_BHI);
                ldsm_x4(laddr, bl[np * 2][0], bl[np * 2 + 1][0],
                               bl[np * 2][1], bl[np * 2 + 1][1]);
            }
#pragma unroll
            for (int mt = 0; mt < 2; mt++) {
                uint32_t aaddr = sbase + OFF_AHI +
                                 (wm * 32 + mt * 16 + lrow) * LDS_STRB + kbyte;
                uint32_t ah0, ah1, ah2, ah3, al0, al1, al2, al3;
                ldsm_x4(aaddr, ah0, ah1, ah2, ah3);
                ldsm_x4(aaddr + (OFF_ALO - OFF_AHI), al0, al1, al2, al3);
#pragma unroll
                for (int nt = 0; nt < 8; nt++) {
                    mma_bf16(acc[mt][nt], ah0, ah1, ah2, ah3, bh[nt][0], bh[nt][1]);
                    mma_bf16(acc[mt][nt], ah0, ah1, ah2, ah3, bl[nt][0], bl[nt][1]);
                    mma_bf16(acc[mt][nt], al0, al1, al2, al3, bh[nt][0], bh[nt][1]);
                }
            }
        }
        __syncthreads();
    }

    const int qrow = lane >> 2;
    const int qcol = (lane & 3) * 2;
#pragma unroll
    for (int mt = 0; mt < 2; mt++) {
        const int r0 = m0 + wm * 32 + mt * 16 + qrow;
#pragma unroll
        for (int nt = 0; nt < 8; nt++) {
            const int c = n0 + wn * 64 + nt * 8 + qcol;
            *reinterpret_cast<float2*>(&C[(size_t)r0 * N + c]) =
                make_float2(acc[mt][nt][0], acc[mt][nt][1]);
            *reinterpret_cast<float2*>(&C[(size_t)(r0 + 8) * N + c]) =
                make_float2(acc[mt][nt][2], acc[mt][nt][3]);
        }
    }
}

// ---------------------------------------------------------------------------
// RoPE + RMSNorm (in-place on q and k). One warp per (b,t,h) row.
// ---------------------------------------------------------------------------
__global__ __launch_bounds__(128)
void rope_rms_kernel(float* __restrict__ q, float* __restrict__ k,
                     const float* __restrict__ cs, const float* __restrict__ sn)
{
    const int gwarp = (blockIdx.x * blockDim.x + threadIdx.x) >> 5;
    const int lane  = threadIdx.x & 31;
    const int h  = gwarp & (NHEAD - 1);
    const int bt = gwarp >> 4;
    const int t  = bt & (SEQ - 1);
    const size_t base = (size_t)bt * CDIM + h * HDIM;

    const float c1 = cs[t * HDIM + lane];
    const float c2 = cs[t * HDIM + 32 + lane];
    const float s1 = sn[t * HDIM + lane];
    const float s2 = sn[t * HDIM + 32 + lane];

    {
        float x1 = q[base + lane];
        float x2 = q[base + 32 + lane];
        float r1 = x1 * c1 - x2 * s1;
        float r2 = x2 * c2 + x1 * s2;
        float ss = r1 * r1 + r2 * r2;
#pragma unroll
        for (int off = 16; off > 0; off >>= 1)
            ss += __shfl_xor_sync(0xffffffffu, ss, off);
        float inv = rsqrtf(ss * (1.0f / 64.0f) + 1e-6f);
        q[base + lane]      = r1 * inv;
        q[base + 32 + lane] = r2 * inv;
    }
    {
        float x1 = k[base + lane];
        float x2 = k[base + 32 + lane];
        float r1 = x1 * c1 - x2 * s1;
        float r2 = x2 * c2 + x1 * s2;
        float ss = r1 * r1 + r2 * r2;
#pragma unroll
        for (int off = 16; off > 0; off >>= 1)
            ss += __shfl_xor_sync(0xffffffffu, ss, off);
        float inv = rsqrtf(ss * (1.0f / 64.0f) + 1e-6f);
        k[base + lane]      = r1 * inv;
        k[base + 32 + lane] = r2 * inv;
    }
}

// ---------------------------------------------------------------------------
// Tensor-core flash attention (tf32 mma, fp32 accum, online softmax).
// Block: 256 threads = 8 warps; each warp owns 16 q-rows (QTILE=128).
// K loop: chunks of 64 rows. Q held in registers as tf32 A-fragments
// (pre-scaled by 1/sqrt(D)); P round-trips through smem for the PV mma.
// Smem rows padded to 68 floats -> conflict-free fragment lds.
// ---------------------------------------------------------------------------
#define QT    128
#define KC    64
#define PSTR  68
#define ATN_SMEM ((KC + KC + QT) * PSTR * (int)sizeof(float))   // 69632

__global__ __launch_bounds__(256)
void attn_tc_kernel(const float* __restrict__ Q, const float* __restrict__ K,
                    const float* __restrict__ V, float* __restrict__ Y)
{
    extern __shared__ float smf[];
    float* Ks = smf;                   // [KC][PSTR]
    float* Vs = Ks + KC * PSTR;        // [KC][PSTR]
    float* Ps = Vs + KC * PSTR;        // [QT][PSTR]  (also Q staging)

    const int b    = blockIdx.z;
    const int h    = blockIdx.y;
    const int qt   = blockIdx.x;
    const int tid  = threadIdx.x;
    const int warp = tid >> 5;
    const int lane = tid & 31;
    const int lr   = lane >> 2;        // 0..7
    const int lc   = lane & 3;         // 0..3
    const float scale = 0.125f;        // 1/sqrt(64)

    const float* qbase = Q + ((size_t)b * SEQ + qt * QT) * CDIM + h * HDIM;
    const float* kbase = K + (size_t)b * SEQ * CDIM + h * HDIM;
    const float* vbase = V + (size_t)b * SEQ * CDIM + h * HDIM;

    // Stage Q tile (128x64) into Ps, then build per-warp tf32 A-fragments.
    for (int i = tid; i < QT * 16; i += 256) {
        int r  = i >> 4;
        int c4 = (i & 15) * 4;
        float4 v = *reinterpret_cast<const float4*>(&qbase[(size_t)r * CDIM + c4]);
        Ps[r * PSTR + c4 + 0] = v.x; Ps[r * PSTR + c4 + 1] = v.y;
        Ps[r * PSTR + c4 + 2] = v.z; Ps[r * PSTR + c4 + 3] = v.w;
    }
    __syncthreads();

    uint32_t qa[8][4];
    {
        const float* qp = Ps + (warp * 16 + lr) * PSTR;
#pragma unroll
        for (int ks = 0; ks < 8; ks++) {
            qa[ks][0] = f2tf32(qp[ks * 8 + lc] * scale);
            qa[ks][1] = f2tf32(qp[8 * PSTR + ks * 8 + lc] * scale);
            qa[ks][2] = f2tf32(qp[ks * 8 + lc + 4] * scale);
            qa[ks][3] = f2tf32(qp[8 * PSTR + ks * 8 + lc + 4] * scale);
        }
    }

    float m[2] = {-1e30f, -1e30f};
    float l[2] = {0.0f, 0.0f};
    float o[8][4];
#pragma unroll
    for (int nt = 0; nt < 8; nt++)
#pragma unroll
        for (int j = 0; j < 4; j++) o[nt][j] = 0.0f;

    for (int kt = 0; kt < SEQ; kt += KC) {
        // Load K,V chunk (64x64 each) fp32 into smem.
        for (int i = tid; i < KC * 16; i += 256) {
            int r  = i >> 4;
            int c4 = (i & 15) * 4;
            float4 vk = *reinterpret_cast<const float4*>(&kbase[(size_t)(kt + r) * CDIM + c4]);
            Ks[r * PSTR + c4 + 0] = vk.x; Ks[r * PSTR + c4 + 1] = vk.y;
            Ks[r * PSTR + c4 + 2] = vk.z; Ks[r * PSTR + c4 + 3] = vk.w;
            float4 vv = *reinterpret_cast<const float4*>(&vbase[(size_t)(kt + r) * CDIM + c4]);
            Vs[r * PSTR + c4 + 0] = vv.x; Vs[r * PSTR + c4 + 1] = vv.y;
            Vs[r * PSTR + c4 + 2] = vv.z; Vs[r * PSTR + c4 + 3] = vv.w;
        }
        __syncthreads();

        // S = (Q*scale) @ K^T : 8 n-tiles of 8 cols, contraction D=64 (8 k8 steps)
        float p[8][4];
#pragma unroll
        for (int nt = 0; nt < 8; nt++) {
            float acc[4] = {0.0f, 0.0f, 0.0f, 0.0f};
            const float* kp = Ks + (nt * 8 + lr) * PSTR;
#pragma unroll
            for (int ks = 0; ks < 8; ks++) {
                uint32_t b0 = f2tf32(kp[ks * 8 + lc]);
                uint32_t b1 = f2tf32(kp[ks * 8 + lc + 4]);
                mma_tf32(acc, qa[ks][0], qa[ks][1], qa[ks][2], qa[ks][3], b0, b1);
            }
            p[nt][0] = acc[0]; p[nt][1] = acc[1]; p[nt][2] = acc[2]; p[nt][3] = acc[3];
        }

        // Online softmax. Register halves: {0,1} -> row lr; {2,3} -> row lr+8.
#pragma unroll
        for (int half = 0; half < 2; half++) {
            const int j0 = half * 2;
            float mx = -1e30f;
#pragma unroll
            for (int nt = 0; nt < 8; nt++)
                mx = fmaxf(mx, fmaxf(p[nt][j0], p[nt][j0 + 1]));
            mx = fmaxf(mx, __shfl_xor_sync(0xffffffffu, mx, 1));
            mx = fmaxf(mx, __shfl_xor_sync(0xffffffffu, mx, 2));
            float mnew  = fmaxf(m[half], mx);
            float alpha = __expf(m[half] - mnew);
            float rsum = 0.0f;
#pragma unroll
            for (int nt = 0; nt < 8; nt++) {
                float p0 = __expf(p[nt][j0]     - mnew);
                float p1 = __expf(p[nt][j0 + 1] - mnew);
                p[nt][j0]     = p0;
                p[nt][j0 + 1] = p1;
                rsum += p0 + p1;
            }
            rsum += __shfl_xor_sync(0xffffffffu, rsum, 1);
            rsum += __shfl_xor_sync(0xffffffffu, rsum, 2);
            l[half] = l[half] * alpha + rsum;
            m[half] = mnew;
#pragma unroll
            for (int nt = 0; nt < 8; nt++) {
                o[nt][j0]     *= alpha;
                o[nt][j0 + 1] *= alpha;
            }
        }

        // Write P to smem (rows warp*16 + lr and +8)
        {
            float* pr0 = Ps + (warp * 16 + lr) * PSTR;
            float* pr1 = pr0 + 8 * PSTR;
#pragma unroll
            for (int nt = 0; nt < 8; nt++) {
                *reinterpret_cast<float2*>(pr0 + nt * 8 + lc * 2) = make_float2(p[nt][0], p[nt][1]);
                *reinterpret_cast<float2*>(pr1 + nt * 8 + lc * 2) = make_float2(p[nt][2], p[nt][3]);
            }
        }
        __syncthreads();

        // O += P @ V : contraction over 64 k-rows (8 k8 steps), 8 d-tiles
        {
            const float* pp = Ps + (warp * 16 + lr) * PSTR;
#pragma unroll
            for (int ks = 0; ks < 8; ks++) {
                uint32_t a0 = f2tf32(pp[ks * 8 + lc]);
                uint32_t a1 = f2tf32(pp[8 * PSTR + ks * 8 + lc]);
                uint32_t a2 = f2tf32(pp[ks * 8 + lc + 4]);
                uint32_t a3 = f2tf32(pp[8 * PSTR + ks * 8 + lc + 4]);
                const float* vp0 = Vs + (ks * 8 + lc) * PSTR;
                const float* vp1 = vp0 + 4 * PSTR;
#pragma unroll
                for (int nt = 0; nt < 8; nt++) {
                    uint32_t b0 = f2tf32(vp0[nt * 8 + lr]);
                    uint32_t b1 = f2tf32(vp1[nt * 8 + lr]);
                    mma_tf32(o[nt], a0, a1, a2, a3, b0, b1);
                }
            }
        }
        __syncthreads();
    }

    // Epilogue: normalize, write to Y (B,T,H,D)
    const float inv0 = 1.0f / l[0];
    const float inv1 = 1.0f / l[1];
    float* yb = Y + ((size_t)b * SEQ + qt * QT + warp * 16 + lr) * CDIM + h * HDIM;
#pragma unroll
    for (int nt = 0; nt < 8; nt++) {
        *reinterpret_cast<float2*>(yb + nt * 8 + lc * 2) =
            make_float2(o[nt][0] * inv0, o[nt][1] * inv0);
        *reinterpret_cast<float2*>(yb + 8 * CDIM + nt * 8 + lc * 2) =
            make_float2(o[nt][2] * inv1, o[nt][3] * inv1);
    }
}

// ---------------------------------------------------------------------------
// kernel_launch
// Inputs (metadata order): x, cos, sin, Wq, Wk, Wv, Wo
// ---------------------------------------------------------------------------
extern "C" void kernel_launch(void* const* d_in, const int* in_sizes, int n_in,
                              void* d_out, int out_size)
{
    const float* x   = (const float*)d_in[0];
    const float* cs  = (const float*)d_in[1];
    const float* sn  = (const float*)d_in[2];
    const float* Wq  = (const float*)d_in[3];
    const float* Wk  = (const float*)d_in[4];
    const float* Wv  = (const float*)d_in[5];
    const float* Wo  = (const float*)d_in[6];
    float* out = (float*)d_out;

    float *q, *k, *v, *y;
    cudaGetSymbolAddress((void**)&q, g_q);
    cudaGetSymbolAddress((void**)&k, g_k);
    cudaGetSymbolAddress((void**)&v, g_v);
    cudaGetSymbolAddress((void**)&y, g_y);
    __nv_bfloat16 *xhi, *xlo, *yhi, *ylo, *whi, *wlo;
    cudaGetSymbolAddress((void**)&xhi, g_xhi);
    cudaGetSymbolAddress((void**)&xlo, g_xlo);
    cudaGetSymbolAddress((void**)&yhi, g_yhi);
    cudaGetSymbolAddress((void**)&ylo, g_ylo);
    cudaGetSymbolAddress((void**)&whi, g_whi);
    cudaGetSymbolAddress((void**)&wlo, g_wlo);

    cudaFuncSetAttribute(attn_tc_kernel, cudaFuncAttributeMaxDynamicSharedMemorySize, ATN_SMEM);
    cudaFuncSetAttribute(gemm_mma_kernel, cudaFuncAttributeMaxDynamicSharedMemorySize, GEMM_SMEM);

    const size_t wsz = (size_t)CDIM * CDIM;    // 1M elements per weight

    // Split x and weights into bf16 hi/lo pairs
    {
        int n4 = (int)((size_t)MROWS * CDIM / 4);
        cvt_bf16x2_kernel<<<(n4 + 255) / 256, 256>>>(
            (const float4*)x, (__nv_bfloat162*)xhi, (__nv_bfloat162*)xlo, n4);
        int w4 = (int)(wsz / 4);
        cvt_bf16x2_kernel<<<(w4 + 255) / 256, 256>>>(
            (const float4*)Wq, (__nv_bfloat162*)(whi + 0 * wsz), (__nv_bfloat162*)(wlo + 0 * wsz), w4);
        cvt_bf16x2_kernel<<<(w4 + 255) / 256, 256>>>(
            (const float4*)Wk, (__nv_bfloat162*)(whi + 1 * wsz), (__nv_bfloat162*)(wlo + 1 * wsz), w4);
        cvt_bf16x2_kernel<<<(w4 + 255) / 256, 256>>>(
            (const float4*)Wv, (__nv_bfloat162*)(whi + 2 * wsz), (__nv_bfloat162*)(wlo + 2 * wsz), w4);
        cvt_bf16x2_kernel<<<(w4 + 255) / 256, 256>>>(
            (const float4*)Wo, (__nv_bfloat162*)(whi + 3 * wsz), (__nv_bfloat162*)(wlo + 3 * wsz), w4);
    }

    dim3 ggrid(CDIM / 128, MROWS / 128);   // (8, 64)
    gemm_mma_kernel<<<ggrid, 256, GEMM_SMEM>>>(xhi, xlo, whi + 0 * wsz, wlo + 0 * wsz, q, MROWS, CDIM, CDIM);
    gemm_mma_kernel<<<ggrid, 256, GEMM_SMEM>>>(xhi, xlo, whi + 1 * wsz, wlo + 1 * wsz, k, MROWS, CDIM, CDIM);
    gemm_mma_kernel<<<ggrid, 256, GEMM_SMEM>>>(xhi, xlo, whi + 2 * wsz, wlo + 2 * wsz, v, MROWS, CDIM, CDIM);

    int nwarps = BATCH * SEQ * NHEAD;
    rope_rms_kernel<<<nwarps / 4, 128>>>(q, k, cs, sn);

    dim3 agrid(SEQ / QT, NHEAD, BATCH);    // (16, 16, 4)
    attn_tc_kernel<<<agrid, 256, ATN_SMEM>>>(q, k, v, y);

    {
        int n4 = (int)((size_t)MROWS * CDIM / 4);
        cvt_bf16x2_kernel<<<(n4 + 255) / 256, 256>>>(
            (const float4*)y, (__nv_bfloat162*)yhi, (__nv_bfloat162*)ylo, n4);
    }
    gemm_mma_kernel<<<ggrid, 256, GEMM_SMEM>>>(yhi, ylo, whi + 3 * wsz, wlo + 3 * wsz, out, MROWS, CDIM, CDIM);
}